// round 3
// baseline (speedup 1.0000x reference)
#include <cuda_runtime.h>
#include <cuda_bf16.h>
#include <math.h>

#define BB 8
#define TT 2048
#define CC 1024
#define MM (BB * TT)   // 16384 rows

// ---------------- scratch (static device globals; no allocation) -------------
__device__ float g_q[(size_t)MM * CC];   // 64 MB
__device__ float g_k[(size_t)MM * CC];   // 64 MB
__device__ float g_vw[MM];               // per-token v·w_eff (incl. c0)
__device__ float g_weff[CC];
__device__ float g_u[CC];
__device__ float g_scal[2];              // [0]=c0, [1]=const_out

// ---------------- packed fp32x2 helpers (sm_100+ only via PTX) ---------------
__device__ __forceinline__ void ffma2(unsigned long long &d,
                                      unsigned long long a,
                                      unsigned long long b) {
    asm("fma.rn.f32x2 %0, %1, %2, %0;" : "+l"(d) : "l"(a), "l"(b));
}
__device__ __forceinline__ unsigned long long pk2(float x, float y) {
    unsigned long long r;
    asm("mov.b64 %0, {%1, %2};" : "=l"(r) : "f"(x), "f"(y));
    return r;
}
__device__ __forceinline__ void upk2(float &x, float &y, unsigned long long v) {
    asm("mov.b64 {%0, %1}, %2;" : "=f"(x), "=f"(y) : "l"(v));
}

// ---------------- weight folding ---------------------------------------------
// w_eff[c] = sum_d W_fc[d] * W_proj[d, c]
__global__ void fold_weff(const float* __restrict__ W_proj,
                          const float* __restrict__ W_fc) {
    int c = blockIdx.x * blockDim.x + threadIdx.x;
    float s = 0.f;
    for (int d = 0; d < CC; d++) s += W_fc[d] * W_proj[d * CC + c];
    g_weff[c] = s;
}

// u[c] = sum_d w_eff[d] * W_attn[2048 + d, c]
__global__ void fold_u(const float* __restrict__ W_attn) {
    int c = blockIdx.x * blockDim.x + threadIdx.x;
    const float* Wv = W_attn + (size_t)2 * CC * CC;
    float s = 0.f;
    for (int d = 0; d < CC; d++) s += g_weff[d] * Wv[d * CC + c];
    g_u[c] = s;
}

// c0 = sum_d w_eff[d]*b_attn[2048+d];  const_out = sum_d W_fc[d]*b_proj[d] + b_fc
__global__ void fold_scalars(const float* __restrict__ W_fc,
                             const float* __restrict__ b_proj,
                             const float* __restrict__ b_fc,
                             const float* __restrict__ b_attn) {
    __shared__ float s1[1024];
    __shared__ float s2[1024];
    int t = threadIdx.x;
    s1[t] = g_weff[t] * b_attn[2 * CC + t];
    s2[t] = W_fc[t] * b_proj[t];
    __syncthreads();
    for (int off = 512; off > 0; off >>= 1) {
        if (t < off) { s1[t] += s1[t + off]; s2[t] += s2[t + off]; }
        __syncthreads();
    }
    if (t == 0) { g_scal[0] = s1[0]; g_scal[1] = s2[0] + b_fc[0]; }
}

// vw[row] = x[row,:]·u + c0    (one warp per row)
__global__ void vw_kernel(const float* __restrict__ x) {
    int warp = threadIdx.x >> 5, lane = threadIdx.x & 31;
    int row = blockIdx.x * 8 + warp;
    const float* xr = x + (size_t)row * CC;
    float s = 0.f;
    for (int c = lane; c < CC; c += 32) s += xr[c] * g_u[c];
    #pragma unroll
    for (int off = 16; off; off >>= 1) s += __shfl_xor_sync(0xffffffffu, s, off);
    if (lane == 0) g_vw[row] = s + g_scal[0];
}

// ---------------- q/k projection: [16384 x 1024] @ [2048 x 1024]^T -----------
// 64x64 tile, 256 threads, 4x4 per thread, f32x2 packed accumulators.
__global__ __launch_bounds__(256) void qk_gemm(const float* __restrict__ x,
                                               const float* __restrict__ W,
                                               const float* __restrict__ bias) {
    __shared__ float As[16][64];
    __shared__ float Bs[16][64];
    int bm = blockIdx.y * 64;
    int bn = blockIdx.x * 64;
    int tid = threadIdx.x;
    int tx = tid & 15, ty = tid >> 4;
    int lr = tid >> 2;            // 0..63 row within tile
    int lk = (tid & 3) << 2;      // k offset 0,4,8,12

    unsigned long long acc[4][2];
    #pragma unroll
    for (int r = 0; r < 4; r++) { acc[r][0] = 0ull; acc[r][1] = 0ull; }

    const float* Aptr = x + (size_t)(bm + lr) * CC;
    const float* Bptr = W + (size_t)(bn + lr) * CC;

    for (int k0 = 0; k0 < CC; k0 += 16) {
        float4 av = *reinterpret_cast<const float4*>(Aptr + k0 + lk);
        float4 bv = *reinterpret_cast<const float4*>(Bptr + k0 + lk);
        __syncthreads();
        As[lk + 0][lr] = av.x; As[lk + 1][lr] = av.y;
        As[lk + 2][lr] = av.z; As[lk + 3][lr] = av.w;
        Bs[lk + 0][lr] = bv.x; Bs[lk + 1][lr] = bv.y;
        Bs[lk + 2][lr] = bv.z; Bs[lk + 3][lr] = bv.w;
        __syncthreads();
        #pragma unroll
        for (int kk = 0; kk < 16; kk++) {
            float4 a = *reinterpret_cast<const float4*>(&As[kk][ty << 2]);
            float4 b = *reinterpret_cast<const float4*>(&Bs[kk][tx << 2]);
            unsigned long long b01 = pk2(b.x, b.y);
            unsigned long long b23 = pk2(b.z, b.w);
            unsigned long long a0 = pk2(a.x, a.x);
            unsigned long long a1 = pk2(a.y, a.y);
            unsigned long long a2 = pk2(a.z, a.z);
            unsigned long long a3 = pk2(a.w, a.w);
            ffma2(acc[0][0], a0, b01); ffma2(acc[0][1], a0, b23);
            ffma2(acc[1][0], a1, b01); ffma2(acc[1][1], a1, b23);
            ffma2(acc[2][0], a2, b01); ffma2(acc[2][1], a2, b23);
            ffma2(acc[3][0], a3, b01); ffma2(acc[3][1], a3, b23);
        }
    }

    int n = bn + (tx << 2);
    float b0 = bias[n], b1 = bias[n + 1], b2 = bias[n + 2], b3 = bias[n + 3];
    // whole 64-wide tile lies fully in q (n<1024) or k region (1024%64==0)
    float* outbase = (n < CC) ? g_q : (g_k - CC);
    #pragma unroll
    for (int r = 0; r < 4; r++) {
        int row = bm + (ty << 2) + r;
        float v0, v1, v2, v3;
        upk2(v0, v1, acc[r][0]);
        upk2(v2, v3, acc[r][1]);
        float4 out = make_float4(v0 + b0, v1 + b1, v2 + b2, v3 + b3);
        *reinterpret_cast<float4*>(outbase + (size_t)row * CC + n) = out;
    }
}

// ---------------- fused attention: S = qk^T, online softmax, scalar V --------
__global__ __launch_bounds__(256) void attn_kernel(float* __restrict__ out) {
    __shared__ float As[16][64];
    __shared__ float Bs[16][64];
    __shared__ float vws[64];
    const float SCALE = 0.03125f;  // 1024^-0.5

    int b = blockIdx.y;
    int q0 = blockIdx.x * 64;
    int tid = threadIdx.x;
    int tx = tid & 15, ty = tid >> 4;
    int lr = tid >> 2;
    int lk = (tid & 3) << 2;

    const float* qbase = g_q + ((size_t)(b * TT + q0)) * CC;
    const float* kbb = g_k + (size_t)b * TT * CC;

    float m[4], l[4], o[4];
    #pragma unroll
    for (int r = 0; r < 4; r++) { m[r] = -1e30f; l[r] = 0.f; o[r] = 0.f; }

    for (int s0 = 0; s0 < TT; s0 += 64) {
        __syncthreads();   // prev tile's vws readers done
        if (tid < 64) vws[tid] = g_vw[b * TT + s0 + tid];

        unsigned long long acc[4][2];
        #pragma unroll
        for (int r = 0; r < 4; r++) { acc[r][0] = 0ull; acc[r][1] = 0ull; }

        const float* kbase = kbb + (size_t)s0 * CC;
        for (int k0 = 0; k0 < CC; k0 += 16) {
            float4 av = *reinterpret_cast<const float4*>(qbase + (size_t)lr * CC + k0 + lk);
            float4 bv = *reinterpret_cast<const float4*>(kbase + (size_t)lr * CC + k0 + lk);
            __syncthreads();
            As[lk + 0][lr] = av.x; As[lk + 1][lr] = av.y;
            As[lk + 2][lr] = av.z; As[lk + 3][lr] = av.w;
            Bs[lk + 0][lr] = bv.x; Bs[lk + 1][lr] = bv.y;
            Bs[lk + 2][lr] = bv.z; Bs[lk + 3][lr] = bv.w;
            __syncthreads();
            #pragma unroll
            for (int kk = 0; kk < 16; kk++) {
                float4 a = *reinterpret_cast<const float4*>(&As[kk][ty << 2]);
                float4 bq = *reinterpret_cast<const float4*>(&Bs[kk][tx << 2]);
                unsigned long long b01 = pk2(bq.x, bq.y);
                unsigned long long b23 = pk2(bq.z, bq.w);
                unsigned long long a0 = pk2(a.x, a.x);
                unsigned long long a1 = pk2(a.y, a.y);
                unsigned long long a2 = pk2(a.z, a.z);
                unsigned long long a3 = pk2(a.w, a.w);
                ffma2(acc[0][0], a0, b01); ffma2(acc[0][1], a0, b23);
                ffma2(acc[1][0], a1, b01); ffma2(acc[1][1], a1, b23);
                ffma2(acc[2][0], a2, b01); ffma2(acc[2][1], a2, b23);
                ffma2(acc[3][0], a3, b01); ffma2(acc[3][1], a3, b23);
            }
        }

        // online softmax update with scalar "value" vws
        float vw0 = vws[(tx << 2) + 0];
        float vw1 = vws[(tx << 2) + 1];
        float vw2 = vws[(tx << 2) + 2];
        float vw3 = vws[(tx << 2) + 3];
        #pragma unroll
        for (int r = 0; r < 4; r++) {
            float s0v, s1v, s2v, s3v;
            upk2(s0v, s1v, acc[r][0]);
            upk2(s2v, s3v, acc[r][1]);
            s0v *= SCALE; s1v *= SCALE; s2v *= SCALE; s3v *= SCALE;
            float tmax = fmaxf(fmaxf(s0v, s1v), fmaxf(s2v, s3v));
            #pragma unroll
            for (int off = 8; off; off >>= 1)
                tmax = fmaxf(tmax, __shfl_xor_sync(0xffffffffu, tmax, off, 16));
            float mn = fmaxf(m[r], tmax);
            float corr = __expf(m[r] - mn);
            float p0 = __expf(s0v - mn);
            float p1 = __expf(s1v - mn);
            float p2 = __expf(s2v - mn);
            float p3 = __expf(s3v - mn);
            float psum = p0 + p1 + p2 + p3;
            float osum = p0 * vw0 + p1 * vw1 + p2 * vw2 + p3 * vw3;
            #pragma unroll
            for (int off = 8; off; off >>= 1) {
                psum += __shfl_xor_sync(0xffffffffu, psum, off, 16);
                osum += __shfl_xor_sync(0xffffffffu, osum, off, 16);
            }
            l[r] = l[r] * corr + psum;
            o[r] = o[r] * corr + osum;
            m[r] = mn;
        }
    }

    if (tx == 0) {
        float co = g_scal[1];
        #pragma unroll
        for (int r = 0; r < 4; r++)
            out[b * TT + q0 + (ty << 2) + r] = o[r] / l[r] + co;
    }
}

// ---------------- launch ------------------------------------------------------
extern "C" void kernel_launch(void* const* d_in, const int* in_sizes, int n_in,
                              void* d_out, int out_size) {
    const float* x      = (const float*)d_in[0];
    const float* W_attn = (const float*)d_in[1];
    const float* b_attn = (const float*)d_in[2];
    const float* W_proj = (const float*)d_in[3];
    const float* b_proj = (const float*)d_in[4];
    const float* W_fc   = (const float*)d_in[5];
    const float* b_fc   = (const float*)d_in[6];
    float* out = (float*)d_out;

    fold_weff<<<4, 256>>>(W_proj, W_fc);
    fold_u<<<4, 256>>>(W_attn);
    fold_scalars<<<1, 1024>>>(W_fc, b_proj, b_fc, b_attn);
    vw_kernel<<<MM / 8, 256>>>(x);
    qk_gemm<<<dim3(2 * CC / 64, MM / 64), 256>>>(x, W_attn, b_attn);
    attn_kernel<<<dim3(TT / 64, BB), 256>>>(out);
}

// round 11
// speedup vs baseline: 2.1363x; 2.1363x over previous
#include <cuda_runtime.h>
#include <cuda_bf16.h>
#include <cstdint>
#include <math.h>

#define BB 8
#define TT 2048
#define CC 1024
#define MM (BB * TT)   // 16384 rows

// ---------------- scratch (uint4-backed => guaranteed 16B alignment) ---------
// NOTE: these are referenced ONLY from device code (never passed from host).
__device__ uint4 g_xh4[(size_t)MM * CC / 8];
__device__ uint4 g_xl4[(size_t)MM * CC / 8];
__device__ uint4 g_wh4[(size_t)2 * CC * CC / 8];
__device__ uint4 g_wl4[(size_t)2 * CC * CC / 8];
__device__ uint4 g_qh4[(size_t)MM * CC / 8];
__device__ uint4 g_ql4[(size_t)MM * CC / 8];
__device__ uint4 g_kh4[(size_t)MM * CC / 8];
__device__ uint4 g_kl4[(size_t)MM * CC / 8];
__device__ float g_vw[MM];
__device__ float g_weff[CC];
__device__ float g_u[CC];
__device__ float g_scal[2];              // [0]=c0, [1]=const_out

#define G_XH ((__nv_bfloat16*)g_xh4)
#define G_XL ((__nv_bfloat16*)g_xl4)
#define G_WH ((__nv_bfloat16*)g_wh4)
#define G_WL ((__nv_bfloat16*)g_wl4)
#define G_QH ((__nv_bfloat16*)g_qh4)
#define G_QL ((__nv_bfloat16*)g_ql4)
#define G_KH ((__nv_bfloat16*)g_kh4)
#define G_KL ((__nv_bfloat16*)g_kl4)

// ================= base-ISA helpers ==========================================
__device__ __forceinline__ uint32_t smem_u32(const void* p) {
    uint32_t a;
    asm("{ .reg .u64 t; cvta.to.shared.u64 t, %1; cvt.u32.u64 %0, t; }"
        : "=r"(a) : "l"(p));
    return a;
}
__device__ __forceinline__ void cp16(uint32_t sm, const void* g) {
    asm volatile("cp.async.cg.shared.global [%0], [%1], 16;" :: "r"(sm), "l"(g));
}
#define CP_COMMIT() asm volatile("cp.async.commit_group;" ::: "memory")
#define CP_WAIT(n)  asm volatile("cp.async.wait_group %0;" :: "n"(n) : "memory")

__device__ __forceinline__ uint32_t lds32(uint32_t addr) {
    uint32_t v;
    asm volatile("ld.shared.b32 %0, [%1];" : "=r"(v) : "r"(addr));
    return v;
}
__device__ __forceinline__ void mma16816(float* c, const uint32_t* a, const uint32_t* b) {
    asm volatile("mma.sync.aligned.m16n8k16.row.col.f32.bf16.bf16.f32 "
                 "{%0,%1,%2,%3}, {%4,%5,%6,%7}, {%8,%9}, {%0,%1,%2,%3};"
                 : "+f"(c[0]), "+f"(c[1]), "+f"(c[2]), "+f"(c[3])
                 : "r"(a[0]), "r"(a[1]), "r"(a[2]), "r"(a[3]), "r"(b[0]), "r"(b[1]));
}

// ---------------- smem tiles: 128 rows x 64 bf16, padded 144B row stride -----
#define ROWB    144
#define TILE_B  (128 * ROWB)       // 18432
#define STAGE_B (4 * TILE_B)       // 73728 (Ah, Al, Bh, Bl)
#define SMEM_DYN (2 * STAGE_B)     // 147456

__device__ __forceinline__ void cp_tile(uint32_t smtile,
                                        const __nv_bfloat16* __restrict__ src,
                                        int tid) {
    #pragma unroll
    for (int i = 0; i < 4; i++) {
        int blk = tid + i * 256;          // 0..1023 : (row 0..127) x (8 x 16B)
        int r = blk >> 3, cb = blk & 7;
        cp16(smtile + (uint32_t)(r * ROWB + cb * 16),
             src + (size_t)r * CC + cb * 8);
    }
}

// ---------------- one K=64 chunk of MMAs (3 hi/lo passes) --------------------
// PTX ISA m16n8k16 fragments (row.col):
//  a0=(row g, k 2t,2t+1), a1=(g+8, same), a2=(g, k+8), a3=(g+8, k+8)
//  b0=(k 2t,2t+1, col g), b1=(k 2t+8,2t+9, col g)
__device__ __forceinline__ void mma_chunk(uint32_t sAh, uint32_t sAl,
                                          uint32_t sBh, uint32_t sBl,
                                          int lane, int wm, int wn,
                                          float (&acc)[2][8][4]) {
    int g = lane >> 2, t = lane & 3;
    #pragma unroll
    for (int kk = 0; kk < 64; kk += 16) {
        uint32_t kb = (uint32_t)((kk + 2 * t) * 2);
        uint32_t a_h[2][4], a_l[2][4];
        #pragma unroll
        for (int mt = 0; mt < 2; mt++) {
            uint32_t r0 = (uint32_t)((wm * 32 + mt * 16 + g) * ROWB);
            a_h[mt][0] = lds32(sAh + r0 + kb);
            a_h[mt][1] = lds32(sAh + r0 + 8 * ROWB + kb);
            a_h[mt][2] = lds32(sAh + r0 + kb + 16);
            a_h[mt][3] = lds32(sAh + r0 + 8 * ROWB + kb + 16);
            a_l[mt][0] = lds32(sAl + r0 + kb);
            a_l[mt][1] = lds32(sAl + r0 + 8 * ROWB + kb);
            a_l[mt][2] = lds32(sAl + r0 + kb + 16);
            a_l[mt][3] = lds32(sAl + r0 + 8 * ROWB + kb + 16);
        }
        #pragma unroll
        for (int nt = 0; nt < 8; nt++) {
            uint32_t n0 = (uint32_t)((wn * 64 + nt * 8 + g) * ROWB);
            uint32_t bh[2], bl[2];
            bh[0] = lds32(sBh + n0 + kb);
            bh[1] = lds32(sBh + n0 + kb + 16);
            bl[0] = lds32(sBl + n0 + kb);
            bl[1] = lds32(sBl + n0 + kb + 16);
            #pragma unroll
            for (int mt = 0; mt < 2; mt++) {
                mma16816(acc[mt][nt], a_h[mt], bh);
                mma16816(acc[mt][nt], a_h[mt], bl);
                mma16816(acc[mt][nt], a_l[mt], bh);
            }
        }
    }
}

// ---------------- full K=1024 GEMM: double-buffered cp.async pipeline --------
__device__ __forceinline__ void gemm128(uint32_t smb,
                                        const __nv_bfloat16* Ah, const __nv_bfloat16* Al,
                                        const __nv_bfloat16* Bh, const __nv_bfloat16* Bl,
                                        int tid, int lane, int wm, int wn,
                                        float (&acc)[2][8][4]) {
    const int NCH = 16;
    cp_tile(smb + 0 * TILE_B, Ah, tid);
    cp_tile(smb + 1 * TILE_B, Al, tid);
    cp_tile(smb + 2 * TILE_B, Bh, tid);
    cp_tile(smb + 3 * TILE_B, Bl, tid);
    CP_COMMIT();
    for (int c = 0; c < NCH; c++) {
        uint32_t st = smb + (uint32_t)(c & 1) * STAGE_B;
        if (c + 1 < NCH) {
            uint32_t st2 = smb + (uint32_t)((c + 1) & 1) * STAGE_B;
            int co = (c + 1) * 64;
            cp_tile(st2 + 0 * TILE_B, Ah + co, tid);
            cp_tile(st2 + 1 * TILE_B, Al + co, tid);
            cp_tile(st2 + 2 * TILE_B, Bh + co, tid);
            cp_tile(st2 + 3 * TILE_B, Bl + co, tid);
            CP_COMMIT();
            CP_WAIT(1);
        } else {
            CP_WAIT(0);
        }
        __syncthreads();
        mma_chunk(st, st + TILE_B, st + 2 * TILE_B, st + 3 * TILE_B,
                  lane, wm, wn, acc);
        __syncthreads();
    }
}

// ---------------- small prep kernels -----------------------------------------
// IMPORTANT: destinations are device-side symbol references (the R5-R8 bug was
// passing __device__ symbol addresses from HOST code — silently invalid).
__global__ void conv_x(const float* __restrict__ src) {
    int i = blockIdx.x * blockDim.x + threadIdx.x;
    float v = src[i];
    __nv_bfloat16 hb = __float2bfloat16_rn(v);
    G_XH[i] = hb;
    G_XL[i] = __float2bfloat16_rn(v - __bfloat162float(hb));
}
__global__ void conv_w(const float* __restrict__ src) {
    int i = blockIdx.x * blockDim.x + threadIdx.x;
    float v = src[i];
    __nv_bfloat16 hb = __float2bfloat16_rn(v);
    G_WH[i] = hb;
    G_WL[i] = __float2bfloat16_rn(v - __bfloat162float(hb));
}

__global__ void fold_weff(const float* __restrict__ W_proj,
                          const float* __restrict__ W_fc) {
    int c = blockIdx.x * blockDim.x + threadIdx.x;
    float s = 0.f;
    for (int d = 0; d < CC; d++) s += W_fc[d] * W_proj[d * CC + c];
    g_weff[c] = s;
}

__global__ void fold_u(const float* __restrict__ W_attn) {
    int c = blockIdx.x * blockDim.x + threadIdx.x;
    const float* Wv = W_attn + (size_t)2 * CC * CC;
    float s = 0.f;
    for (int d = 0; d < CC; d++) s += g_weff[d] * Wv[d * CC + c];
    g_u[c] = s;
}

__global__ void fold_scalars(const float* __restrict__ W_fc,
                             const float* __restrict__ b_proj,
                             const float* __restrict__ b_fc,
                             const float* __restrict__ b_attn) {
    __shared__ float s1[1024];
    __shared__ float s2[1024];
    int t = threadIdx.x;
    s1[t] = g_weff[t] * b_attn[2 * CC + t];
    s2[t] = W_fc[t] * b_proj[t];
    __syncthreads();
    for (int off = 512; off > 0; off >>= 1) {
        if (t < off) { s1[t] += s1[t + off]; s2[t] += s2[t + off]; }
        __syncthreads();
    }
    if (t == 0) { g_scal[0] = s1[0]; g_scal[1] = s2[0] + b_fc[0]; }
}

__global__ void vw_kernel(const float* __restrict__ x) {
    int warp = threadIdx.x >> 5, lane = threadIdx.x & 31;
    int row = blockIdx.x * 8 + warp;
    const float* xr = x + (size_t)row * CC;
    float s = 0.f;
    for (int c = lane; c < CC; c += 32) s += xr[c] * g_u[c];
    #pragma unroll
    for (int off = 16; off; off >>= 1) s += __shfl_xor_sync(0xffffffffu, s, off);
    if (lane == 0) g_vw[row] = s + g_scal[0];
}

// ================= q/k projection via HMMA ===================================
// grid (16, 128): C[16384, 2048] = Xhl @ W_attn[0:2048]^T + bias -> bf16 hi/lo
__global__ __launch_bounds__(256, 1)
void qk_mma(const float* __restrict__ bias) {
    extern __shared__ char smdyn[];
    __shared__ float s_bias[128];
    uint32_t smb = smem_u32(smdyn);
    int tid = threadIdx.x, lane = tid & 31, wid = tid >> 5;
    int wm = wid & 3, wn = wid >> 2;
    int bm = blockIdx.y * 128, bn = blockIdx.x * 128;

    if (tid < 128) s_bias[tid] = bias[bn + tid];

    float acc[2][8][4];
    #pragma unroll
    for (int mt = 0; mt < 2; mt++)
        #pragma unroll
        for (int nt = 0; nt < 8; nt++)
            #pragma unroll
            for (int e = 0; e < 4; e++) acc[mt][nt][e] = 0.f;

    gemm128(smb,
            G_XH + (size_t)bm * CC, G_XL + (size_t)bm * CC,
            G_WH + (size_t)bn * CC, G_WL + (size_t)bn * CC,
            tid, lane, wm, wn, acc);

    __nv_bfloat16 *dh, *dl;
    int col0;
    if (bn < CC) { dh = G_QH; dl = G_QL; col0 = bn; }
    else         { dh = G_KH; dl = G_KL; col0 = bn - CC; }

    int g = lane >> 2, q = lane & 3;
    #pragma unroll
    for (int mt = 0; mt < 2; mt++)
        #pragma unroll
        for (int hf = 0; hf < 2; hf++) {
            int row = bm + wm * 32 + mt * 16 + hf * 8 + g;
            #pragma unroll
            for (int nt = 0; nt < 8; nt++) {
                int cl = wn * 64 + nt * 8 + q * 2;
                float v0 = acc[mt][nt][hf * 2 + 0] + s_bias[cl];
                float v1 = acc[mt][nt][hf * 2 + 1] + s_bias[cl + 1];
                __nv_bfloat16 h0 = __float2bfloat16_rn(v0);
                __nv_bfloat16 h1 = __float2bfloat16_rn(v1);
                __nv_bfloat16 l0 = __float2bfloat16_rn(v0 - __bfloat162float(h0));
                __nv_bfloat16 l1 = __float2bfloat16_rn(v1 - __bfloat162float(h1));
                uint32_t hp = ((uint32_t)*(uint16_t*)&h1 << 16) | *(uint16_t*)&h0;
                uint32_t lp = ((uint32_t)*(uint16_t*)&l1 << 16) | *(uint16_t*)&l0;
                size_t off = (size_t)row * CC + col0 + cl;
                *reinterpret_cast<uint32_t*>(dh + off) = hp;
                *reinterpret_cast<uint32_t*>(dl + off) = lp;
            }
        }
}

// ================= fused attention via HMMA ==================================
// grid (16, 8): CTA = (q-tile 128 rows, batch); loops 16 s-tiles of 128 keys.
// Per-warp online softmax over its 64 key-columns; column halves merge at end.
__global__ __launch_bounds__(256, 1)
void attn_mma(float* __restrict__ out) {
    extern __shared__ char smdyn[];
    __shared__ float s_vw[128];
    __shared__ float s_m[2][128];
    __shared__ float s_l[2][128];
    __shared__ float s_o[2][128];
    uint32_t smb = smem_u32(smdyn);
    int tid = threadIdx.x, lane = tid & 31, wid = tid >> 5;
    int wm = wid & 3, wn = wid >> 2;
    int g = lane >> 2, q = lane & 3;
    int b = blockIdx.y, q0 = blockIdx.x * 128;
    const float SCALE = 0.03125f;  // 1024^-0.5

    const __nv_bfloat16* Ah = G_QH + (size_t)(b * TT + q0) * CC;
    const __nv_bfloat16* Al = G_QL + (size_t)(b * TT + q0) * CC;

    float m_w[4], l_w[4], o_w[4];   // slot = mt*2+hf -> row wm*32+mt*16+hf*8+g
    #pragma unroll
    for (int s = 0; s < 4; s++) { m_w[s] = -1e30f; l_w[s] = 0.f; o_w[s] = 0.f; }

    for (int st = 0; st < 16; st++) {
        float acc[2][8][4];
        #pragma unroll
        for (int mt = 0; mt < 2; mt++)
            #pragma unroll
            for (int nt = 0; nt < 8; nt++)
                #pragma unroll
                for (int e = 0; e < 4; e++) acc[mt][nt][e] = 0.f;

        const __nv_bfloat16* Bh = G_KH + (size_t)(b * TT + st * 128) * CC;
        const __nv_bfloat16* Bl = G_KL + (size_t)(b * TT + st * 128) * CC;
        gemm128(smb, Ah, Al, Bh, Bl, tid, lane, wm, wn, acc);

        if (tid < 128) s_vw[tid] = g_vw[b * TT + st * 128 + tid];
        __syncthreads();

        #pragma unroll
        for (int mt = 0; mt < 2; mt++)
            #pragma unroll
            for (int hf = 0; hf < 2; hf++) {
                int slot = mt * 2 + hf;
                float mx = -1e30f;
                #pragma unroll
                for (int nt = 0; nt < 8; nt++) {
                    mx = fmaxf(mx, acc[mt][nt][hf * 2 + 0]);
                    mx = fmaxf(mx, acc[mt][nt][hf * 2 + 1]);
                }
                mx = fmaxf(mx, __shfl_xor_sync(0xffffffffu, mx, 1));
                mx = fmaxf(mx, __shfl_xor_sync(0xffffffffu, mx, 2));
                float mn = fmaxf(m_w[slot], mx * SCALE);
                float corr = __expf(m_w[slot] - mn);
                float ps = 0.f, os = 0.f;
                #pragma unroll
                for (int nt = 0; nt < 8; nt++) {
                    int cl = wn * 64 + nt * 8 + q * 2;
                    float p0 = __expf(acc[mt][nt][hf * 2 + 0] * SCALE - mn);
                    float p1 = __expf(acc[mt][nt][hf * 2 + 1] * SCALE - mn);
                    ps += p0 + p1;
                    os += p0 * s_vw[cl] + p1 * s_vw[cl + 1];
                }
                ps += __shfl_xor_sync(0xffffffffu, ps, 1);
                ps += __shfl_xor_sync(0xffffffffu, ps, 2);
                os += __shfl_xor_sync(0xffffffffu, os, 1);
                os += __shfl_xor_sync(0xffffffffu, os, 2);
                l_w[slot] = l_w[slot] * corr + ps;
                o_w[slot] = o_w[slot] * corr + os;
                m_w[slot] = mn;
            }
        __syncthreads();   // s_vw reuse next tile
    }

    if (q == 0) {
        #pragma unroll
        for (int mt = 0; mt < 2; mt++)
            #pragma unroll
            for (int hf = 0; hf < 2; hf++) {
                int slot = mt * 2 + hf;
                int rl = wm * 32 + mt * 16 + hf * 8 + g;
                s_m[wn][rl] = m_w[slot];
                s_l[wn][rl] = l_w[slot];
                s_o[wn][rl] = o_w[slot];
            }
    }
    __syncthreads();
    if (wn == 0 && q == 0) {
        float co = g_scal[1];
        #pragma unroll
        for (int mt = 0; mt < 2; mt++)
            #pragma unroll
            for (int hf = 0; hf < 2; hf++) {
                int rl = wm * 32 + mt * 16 + hf * 8 + g;
                float m0 = s_m[0][rl], m1 = s_m[1][rl];
                float mM = fmaxf(m0, m1);
                float e0 = __expf(m0 - mM), e1 = __expf(m1 - mM);
                float lsum = s_l[0][rl] * e0 + s_l[1][rl] * e1;
                float osum = s_o[0][rl] * e0 + s_o[1][rl] * e1;
                out[b * TT + q0 + rl] = osum / lsum + co;
            }
    }
}

// ---------------- launch ------------------------------------------------------
extern "C" void kernel_launch(void* const* d_in, const int* in_sizes, int n_in,
                              void* d_out, int out_size) {
    const float* x      = (const float*)d_in[0];
    const float* W_attn = (const float*)d_in[1];
    const float* b_attn = (const float*)d_in[2];
    const float* W_proj = (const float*)d_in[3];
    const float* b_proj = (const float*)d_in[4];
    const float* W_fc   = (const float*)d_in[5];
    const float* b_fc   = (const float*)d_in[6];
    float* out = (float*)d_out;

    cudaFuncSetAttribute(qk_mma,   cudaFuncAttributeMaxDynamicSharedMemorySize, SMEM_DYN);
    cudaFuncSetAttribute(attn_mma, cudaFuncAttributeMaxDynamicSharedMemorySize, SMEM_DYN);

    int nx = MM * CC;       // 16777216, divisible by 256
    int nw = 2 * CC * CC;   // 2097152, divisible by 256
    conv_x<<<nx / 256, 256>>>(x);
    conv_w<<<nw / 256, 256>>>(W_attn);
    fold_weff<<<4, 256>>>(W_proj, W_fc);
    fold_u<<<4, 256>>>(W_attn);
    fold_scalars<<<1, 1024>>>(W_fc, b_proj, b_fc, b_attn);
    vw_kernel<<<MM / 8, 256>>>(x);

    qk_mma<<<dim3(16, 128), 256, SMEM_DYN>>>(b_attn);
    attn_mma<<<dim3(16, 8), 256, SMEM_DYN>>>(out);
}

// round 12
// speedup vs baseline: 3.1926x; 1.4944x over previous
#include <cuda_runtime.h>
#include <cuda_bf16.h>
#include <cstdint>
#include <math.h>

#define BB 8
#define TT 2048
#define CC 1024
#define MM (BB * TT)   // 16384 rows

// ---------------- scratch (uint4-backed => guaranteed 16B alignment) ---------
// Referenced ONLY from device code (never passed from host).
__device__ uint4 g_xh4[(size_t)MM * CC / 8];
__device__ uint4 g_xl4[(size_t)MM * CC / 8];
__device__ uint4 g_wh4[(size_t)2 * CC * CC / 8];
__device__ uint4 g_wl4[(size_t)2 * CC * CC / 8];
__device__ uint4 g_qh4[(size_t)MM * CC / 8];
__device__ uint4 g_ql4[(size_t)MM * CC / 8];
__device__ uint4 g_kh4[(size_t)MM * CC / 8];
__device__ uint4 g_kl4[(size_t)MM * CC / 8];
__device__ float g_vw[MM];
__device__ float g_part[64 * CC];        // fold partials (fully overwritten each use)
__device__ float g_weff[CC];
__device__ float g_u[CC];
__device__ float g_scal[2];              // [0]=c0, [1]=const_out

#define G_XH ((__nv_bfloat16*)g_xh4)
#define G_XL ((__nv_bfloat16*)g_xl4)
#define G_WH ((__nv_bfloat16*)g_wh4)
#define G_WL ((__nv_bfloat16*)g_wl4)
#define G_QH ((__nv_bfloat16*)g_qh4)
#define G_QL ((__nv_bfloat16*)g_ql4)
#define G_KH ((__nv_bfloat16*)g_kh4)
#define G_KL ((__nv_bfloat16*)g_kl4)

// ================= base-ISA helpers ==========================================
__device__ __forceinline__ uint32_t smem_u32(const void* p) {
    uint32_t a;
    asm("{ .reg .u64 t; cvta.to.shared.u64 t, %1; cvt.u32.u64 %0, t; }"
        : "=r"(a) : "l"(p));
    return a;
}
__device__ __forceinline__ void cp16(uint32_t sm, const void* g) {
    asm volatile("cp.async.cg.shared.global [%0], [%1], 16;" :: "r"(sm), "l"(g));
}
#define CP_COMMIT() asm volatile("cp.async.commit_group;" ::: "memory")
#define CP_WAIT(n)  asm volatile("cp.async.wait_group %0;" :: "n"(n) : "memory")

__device__ __forceinline__ void ldsm4(uint32_t* r, uint32_t addr) {
    asm volatile("ldmatrix.sync.aligned.m8n8.x4.shared.b16 {%0,%1,%2,%3}, [%4];"
                 : "=r"(r[0]), "=r"(r[1]), "=r"(r[2]), "=r"(r[3]) : "r"(addr));
}
__device__ __forceinline__ void mma16816(float* c, const uint32_t* a,
                                         uint32_t b0, uint32_t b1) {
    asm volatile("mma.sync.aligned.m16n8k16.row.col.f32.bf16.bf16.f32 "
                 "{%0,%1,%2,%3}, {%4,%5,%6,%7}, {%8,%9}, {%0,%1,%2,%3};"
                 : "+f"(c[0]), "+f"(c[1]), "+f"(c[2]), "+f"(c[3])
                 : "r"(a[0]), "r"(a[1]), "r"(a[2]), "r"(a[3]), "r"(b0), "r"(b1));
}

// ---------------- smem tiles: 128 rows x 64 bf16, padded 144B row stride -----
// 144 mod 128 = 16 -> 8 consecutive rows cover all 32 banks: LDSM conflict-free.
#define ROWB    144
#define TILE_B  (128 * ROWB)       // 18432
#define STAGE_B (4 * TILE_B)       // 73728 (Ah, Al, Bh, Bl)
#define SMEM_DYN (2 * STAGE_B)     // 147456

__device__ __forceinline__ void cp_tile(uint32_t smtile,
                                        const __nv_bfloat16* __restrict__ src,
                                        int tid) {
    #pragma unroll
    for (int i = 0; i < 4; i++) {
        int blk = tid + i * 256;          // 0..1023 : (row 0..127) x (8 x 16B)
        int r = blk >> 3, cb = blk & 7;
        cp16(smtile + (uint32_t)(r * ROWB + cb * 16),
             src + (size_t)r * CC + cb * 8);
    }
}

// ---------------- one K=64 chunk of MMAs (3 hi/lo passes), ldmatrix loads ----
// A 16x16 tile via ldmatrix.x4: lane addr row = r0+((l>>3)&1)*8+(l&7),
// col = kk+(l>>4)*8  ->  regs {a0,a1,a2,a3} per PTX m16n8k16 tables.
// B (n-major rows) 16n x 16k via x4 -> regs {b0(nt0), b0(nt1), b1(nt0), b1(nt1)}.
__device__ __forceinline__ void mma_chunk(uint32_t sAh, uint32_t sAl,
                                          uint32_t sBh, uint32_t sBl,
                                          int lane, int wm, int wn,
                                          float (&acc)[2][8][4]) {
    uint32_t loff = (uint32_t)((((lane >> 3) & 1) * 8 + (lane & 7)) * ROWB +
                               ((lane >> 4) * 8) * 2);
    #pragma unroll
    for (int kk = 0; kk < 64; kk += 16) {
        uint32_t kb = loff + (uint32_t)(kk * 2);
        uint32_t a_h[2][4], a_l[2][4], bh[4][4], bl[4][4];
        #pragma unroll
        for (int mt = 0; mt < 2; mt++) {
            uint32_t r0 = (uint32_t)((wm * 32 + mt * 16) * ROWB) + kb;
            ldsm4(a_h[mt], sAh + r0);
            ldsm4(a_l[mt], sAl + r0);
        }
        #pragma unroll
        for (int np = 0; np < 4; np++) {
            uint32_t n0 = (uint32_t)((wn * 64 + np * 16) * ROWB) + kb;
            ldsm4(bh[np], sBh + n0);
            ldsm4(bl[np], sBl + n0);
        }
        #pragma unroll
        for (int mt = 0; mt < 2; mt++)
            #pragma unroll
            for (int np = 0; np < 4; np++) {
                mma16816(acc[mt][2 * np + 0], a_h[mt], bh[np][0], bh[np][2]);
                mma16816(acc[mt][2 * np + 1], a_h[mt], bh[np][1], bh[np][3]);
                mma16816(acc[mt][2 * np + 0], a_h[mt], bl[np][0], bl[np][2]);
                mma16816(acc[mt][2 * np + 1], a_h[mt], bl[np][1], bl[np][3]);
                mma16816(acc[mt][2 * np + 0], a_l[mt], bh[np][0], bh[np][2]);
                mma16816(acc[mt][2 * np + 1], a_l[mt], bh[np][1], bh[np][3]);
            }
    }
}

// ---------------- full K=1024 GEMM: double-buffered cp.async pipeline --------
__device__ __forceinline__ void gemm128(uint32_t smb,
                                        const __nv_bfloat16* Ah, const __nv_bfloat16* Al,
                                        const __nv_bfloat16* Bh, const __nv_bfloat16* Bl,
                                        int tid, int lane, int wm, int wn,
                                        float (&acc)[2][8][4]) {
    const int NCH = 16;
    cp_tile(smb + 0 * TILE_B, Ah, tid);
    cp_tile(smb + 1 * TILE_B, Al, tid);
    cp_tile(smb + 2 * TILE_B, Bh, tid);
    cp_tile(smb + 3 * TILE_B, Bl, tid);
    CP_COMMIT();
    for (int c = 0; c < NCH; c++) {
        uint32_t st = smb + (uint32_t)(c & 1) * STAGE_B;
        if (c + 1 < NCH) {
            uint32_t st2 = smb + (uint32_t)((c + 1) & 1) * STAGE_B;
            int co = (c + 1) * 64;
            cp_tile(st2 + 0 * TILE_B, Ah + co, tid);
            cp_tile(st2 + 1 * TILE_B, Al + co, tid);
            cp_tile(st2 + 2 * TILE_B, Bh + co, tid);
            cp_tile(st2 + 3 * TILE_B, Bl + co, tid);
            CP_COMMIT();
            CP_WAIT(1);
        } else {
            CP_WAIT(0);
        }
        __syncthreads();
        mma_chunk(st, st + TILE_B, st + 2 * TILE_B, st + 3 * TILE_B,
                  lane, wm, wn, acc);
        __syncthreads();
    }
}

// ---------------- small prep kernels -----------------------------------------
__global__ void conv_x(const float* __restrict__ src) {
    int i = blockIdx.x * blockDim.x + threadIdx.x;
    float v = src[i];
    __nv_bfloat16 hb = __float2bfloat16_rn(v);
    G_XH[i] = hb;
    G_XL[i] = __float2bfloat16_rn(v - __bfloat162float(hb));
}
__global__ void conv_w(const float* __restrict__ src) {
    int i = blockIdx.x * blockDim.x + threadIdx.x;
    float v = src[i];
    __nv_bfloat16 hb = __float2bfloat16_rn(v);
    G_WH[i] = hb;
    G_WL[i] = __float2bfloat16_rn(v - __bfloat162float(hb));
}

// ---- two-stage folds: 64 blocks x 16-d slices -> partials -> reduce ---------
__global__ void fold_weff1(const float* __restrict__ W_proj,
                           const float* __restrict__ W_fc) {
    int b = blockIdx.x, t = threadIdx.x;   // 64 blocks x 256 threads
    #pragma unroll
    for (int cg = 0; cg < 4; cg++) {
        int c = cg * 256 + t;
        float s = 0.f;
        #pragma unroll
        for (int i = 0; i < 16; i++) {
            int d = b * 16 + i;
            s += W_fc[d] * W_proj[d * CC + c];
        }
        g_part[b * CC + c] = s;
    }
}
__global__ void fold_weff2() {             // 4 blocks x 256
    int c = blockIdx.x * 256 + threadIdx.x;
    float s = 0.f;
    #pragma unroll
    for (int i = 0; i < 64; i++) s += g_part[i * CC + c];
    g_weff[c] = s;
}
__global__ void fold_u1(const float* __restrict__ W_attn) {
    const float* Wv = W_attn + (size_t)2 * CC * CC;
    int b = blockIdx.x, t = threadIdx.x;
    #pragma unroll
    for (int cg = 0; cg < 4; cg++) {
        int c = cg * 256 + t;
        float s = 0.f;
        #pragma unroll
        for (int i = 0; i < 16; i++) {
            int d = b * 16 + i;
            s += g_weff[d] * Wv[d * CC + c];
        }
        g_part[b * CC + c] = s;
    }
}
__global__ void fold_u2() {
    int c = blockIdx.x * 256 + threadIdx.x;
    float s = 0.f;
    #pragma unroll
    for (int i = 0; i < 64; i++) s += g_part[i * CC + c];
    g_u[c] = s;
}

__global__ void fold_scalars(const float* __restrict__ W_fc,
                             const float* __restrict__ b_proj,
                             const float* __restrict__ b_fc,
                             const float* __restrict__ b_attn) {
    __shared__ float s1[1024];
    __shared__ float s2[1024];
    int t = threadIdx.x;
    s1[t] = g_weff[t] * b_attn[2 * CC + t];
    s2[t] = W_fc[t] * b_proj[t];
    __syncthreads();
    for (int off = 512; off > 0; off >>= 1) {
        if (t < off) { s1[t] += s1[t + off]; s2[t] += s2[t + off]; }
        __syncthreads();
    }
    if (t == 0) { g_scal[0] = s1[0]; g_scal[1] = s2[0] + b_fc[0]; }
}

__global__ void vw_kernel(const float* __restrict__ x) {
    int warp = threadIdx.x >> 5, lane = threadIdx.x & 31;
    int row = blockIdx.x * 8 + warp;
    const float* xr = x + (size_t)row * CC;
    float s = 0.f;
    for (int c = lane; c < CC; c += 32) s += xr[c] * g_u[c];
    #pragma unroll
    for (int off = 16; off; off >>= 1) s += __shfl_xor_sync(0xffffffffu, s, off);
    if (lane == 0) g_vw[row] = s + g_scal[0];
}

// ================= q/k projection via HMMA ===================================
// grid (16, 128): C[16384, 2048] = Xhl @ W_attn[0:2048]^T + bias -> bf16 hi/lo
__global__ __launch_bounds__(256, 1)
void qk_mma(const float* __restrict__ bias) {
    extern __shared__ char smdyn[];
    __shared__ float s_bias[128];
    uint32_t smb = smem_u32(smdyn);
    int tid = threadIdx.x, lane = tid & 31, wid = tid >> 5;
    int wm = wid & 3, wn = wid >> 2;
    int bm = blockIdx.y * 128, bn = blockIdx.x * 128;

    if (tid < 128) s_bias[tid] = bias[bn + tid];

    float acc[2][8][4];
    #pragma unroll
    for (int mt = 0; mt < 2; mt++)
        #pragma unroll
        for (int nt = 0; nt < 8; nt++)
            #pragma unroll
            for (int e = 0; e < 4; e++) acc[mt][nt][e] = 0.f;

    gemm128(smb,
            G_XH + (size_t)bm * CC, G_XL + (size_t)bm * CC,
            G_WH + (size_t)bn * CC, G_WL + (size_t)bn * CC,
            tid, lane, wm, wn, acc);

    __nv_bfloat16 *dh, *dl;
    int col0;
    if (bn < CC) { dh = G_QH; dl = G_QL; col0 = bn; }
    else         { dh = G_KH; dl = G_KL; col0 = bn - CC; }

    int g = lane >> 2, q = lane & 3;
    #pragma unroll
    for (int mt = 0; mt < 2; mt++)
        #pragma unroll
        for (int hf = 0; hf < 2; hf++) {
            int row = bm + wm * 32 + mt * 16 + hf * 8 + g;
            #pragma unroll
            for (int nt = 0; nt < 8; nt++) {
                int cl = wn * 64 + nt * 8 + q * 2;
                float v0 = acc[mt][nt][hf * 2 + 0] + s_bias[cl];
                float v1 = acc[mt][nt][hf * 2 + 1] + s_bias[cl + 1];
                __nv_bfloat16 h0 = __float2bfloat16_rn(v0);
                __nv_bfloat16 h1 = __float2bfloat16_rn(v1);
                __nv_bfloat16 l0 = __float2bfloat16_rn(v0 - __bfloat162float(h0));
                __nv_bfloat16 l1 = __float2bfloat16_rn(v1 - __bfloat162float(h1));
                uint32_t hp = ((uint32_t)*(uint16_t*)&h1 << 16) | *(uint16_t*)&h0;
                uint32_t lp = ((uint32_t)*(uint16_t*)&l1 << 16) | *(uint16_t*)&l0;
                size_t off = (size_t)row * CC + col0 + cl;
                *reinterpret_cast<uint32_t*>(dh + off) = hp;
                *reinterpret_cast<uint32_t*>(dl + off) = lp;
            }
        }
}

// ================= fused attention via HMMA ==================================
// grid (16, 8): CTA = (q-tile 128 rows, batch); loops 16 s-tiles of 128 keys.
__global__ __launch_bounds__(256, 1)
void attn_mma(float* __restrict__ out) {
    extern __shared__ char smdyn[];
    __shared__ float s_vw[128];
    __shared__ float s_m[2][128];
    __shared__ float s_l[2][128];
    __shared__ float s_o[2][128];
    uint32_t smb = smem_u32(smdyn);
    int tid = threadIdx.x, lane = tid & 31, wid = tid >> 5;
    int wm = wid & 3, wn = wid >> 2;
    int g = lane >> 2, q = lane & 3;
    int b = blockIdx.y, q0 = blockIdx.x * 128;
    const float SCALE = 0.03125f;  // 1024^-0.5

    const __nv_bfloat16* Ah = G_QH + (size_t)(b * TT + q0) * CC;
    const __nv_bfloat16* Al = G_QL + (size_t)(b * TT + q0) * CC;

    float m_w[4], l_w[4], o_w[4];
    #pragma unroll
    for (int s = 0; s < 4; s++) { m_w[s] = -1e30f; l_w[s] = 0.f; o_w[s] = 0.f; }

    for (int st = 0; st < 16; st++) {
        float acc[2][8][4];
        #pragma unroll
        for (int mt = 0; mt < 2; mt++)
            #pragma unroll
            for (int nt = 0; nt < 8; nt++)
                #pragma unroll
                for (int e = 0; e < 4; e++) acc[mt][nt][e] = 0.f;

        const __nv_bfloat16* Bh = G_KH + (size_t)(b * TT + st * 128) * CC;
        const __nv_bfloat16* Bl = G_KL + (size_t)(b * TT + st * 128) * CC;
        gemm128(smb, Ah, Al, Bh, Bl, tid, lane, wm, wn, acc);

        if (tid < 128) s_vw[tid] = g_vw[b * TT + st * 128 + tid];
        __syncthreads();

        #pragma unroll
        for (int mt = 0; mt < 2; mt++)
            #pragma unroll
            for (int hf = 0; hf < 2; hf++) {
                int slot = mt * 2 + hf;
                float mx = -1e30f;
                #pragma unroll
                for (int nt = 0; nt < 8; nt++) {
                    mx = fmaxf(mx, acc[mt][nt][hf * 2 + 0]);
                    mx = fmaxf(mx, acc[mt][nt][hf * 2 + 1]);
                }
                mx = fmaxf(mx, __shfl_xor_sync(0xffffffffu, mx, 1));
                mx = fmaxf(mx, __shfl_xor_sync(0xffffffffu, mx, 2));
                float mn = fmaxf(m_w[slot], mx * SCALE);
                float corr = __expf(m_w[slot] - mn);
                float ps = 0.f, os = 0.f;
                #pragma unroll
                for (int nt = 0; nt < 8; nt++) {
                    int cl = wn * 64 + nt * 8 + q * 2;
                    float p0 = __expf(acc[mt][nt][hf * 2 + 0] * SCALE - mn);
                    float p1 = __expf(acc[mt][nt][hf * 2 + 1] * SCALE - mn);
                    ps += p0 + p1;
                    os += p0 * s_vw[cl] + p1 * s_vw[cl + 1];
                }
                ps += __shfl_xor_sync(0xffffffffu, ps, 1);
                ps += __shfl_xor_sync(0xffffffffu, ps, 2);
                os += __shfl_xor_sync(0xffffffffu, os, 1);
                os += __shfl_xor_sync(0xffffffffu, os, 2);
                l_w[slot] = l_w[slot] * corr + ps;
                o_w[slot] = o_w[slot] * corr + os;
                m_w[slot] = mn;
            }
        __syncthreads();   // s_vw reuse next tile
    }

    if (q == 0) {
        #pragma unroll
        for (int mt = 0; mt < 2; mt++)
            #pragma unroll
            for (int hf = 0; hf < 2; hf++) {
                int slot = mt * 2 + hf;
                int rl = wm * 32 + mt * 16 + hf * 8 + g;
                s_m[wn][rl] = m_w[slot];
                s_l[wn][rl] = l_w[slot];
                s_o[wn][rl] = o_w[slot];
            }
    }
    __syncthreads();
    if (wn == 0 && q == 0) {
        float co = g_scal[1];
        #pragma unroll
        for (int mt = 0; mt < 2; mt++)
            #pragma unroll
            for (int hf = 0; hf < 2; hf++) {
                int rl = wm * 32 + mt * 16 + hf * 8 + g;
                float m0 = s_m[0][rl], m1 = s_m[1][rl];
                float mM = fmaxf(m0, m1);
                float e0 = __expf(m0 - mM), e1 = __expf(m1 - mM);
                float lsum = s_l[0][rl] * e0 + s_l[1][rl] * e1;
                float osum = s_o[0][rl] * e0 + s_o[1][rl] * e1;
                out[b * TT + q0 + rl] = osum / lsum + co;
            }
    }
}

// ---------------- launch ------------------------------------------------------
extern "C" void kernel_launch(void* const* d_in, const int* in_sizes, int n_in,
                              void* d_out, int out_size) {
    const float* x      = (const float*)d_in[0];
    const float* W_attn = (const float*)d_in[1];
    const float* b_attn = (const float*)d_in[2];
    const float* W_proj = (const float*)d_in[3];
    const float* b_proj = (const float*)d_in[4];
    const float* W_fc   = (const float*)d_in[5];
    const float* b_fc   = (const float*)d_in[6];
    float* out = (float*)d_out;

    cudaFuncSetAttribute(qk_mma,   cudaFuncAttributeMaxDynamicSharedMemorySize, SMEM_DYN);
    cudaFuncSetAttribute(attn_mma, cudaFuncAttributeMaxDynamicSharedMemorySize, SMEM_DYN);

    int nx = MM * CC;       // divisible by 256
    int nw = 2 * CC * CC;   // divisible by 256
    conv_x<<<nx / 256, 256>>>(x);
    conv_w<<<nw / 256, 256>>>(W_attn);
    fold_weff1<<<64, 256>>>(W_proj, W_fc);
    fold_weff2<<<4, 256>>>();
    fold_u1<<<64, 256>>>(W_attn);
    fold_u2<<<4, 256>>>();
    fold_scalars<<<1, 1024>>>(W_fc, b_proj, b_fc, b_attn);
    vw_kernel<<<MM / 8, 256>>>(x);

    qk_mma<<<dim3(16, 128), 256, SMEM_DYN>>>(b_attn);
    attn_mma<<<dim3(16, 8), 256, SMEM_DYN>>>(out);
}